// round 10
// baseline (speedup 1.0000x reference)
#include <cuda_runtime.h>

#define NN 50000
#define EE 800000
#define NB 148            // persistent grid: <= SM count, all co-resident
#define NT 256
#define CHUNK 338         // ceil(NN / NB)
#define NWARP 4           // warps per block in fused kernel
#define CAP_E 24          // per-warp msg-row cache (edges)
#define CAP_L 64          // per-warp logit cache
#define SMEM_BYTES 49664  // sW 16384 + sx 33280

// ---------------- scratch (device globals; no allocations allowed) ----------
__device__ float g_y[NN * 64];        // y = x @ W_msg + (b_msg + b_edge)
__device__ int   g_counts[NN];
__device__ int   g_offsets[NN];
__device__ int   g_cursor[NN];
__device__ int   g_part[NB];
__device__ int2  g_sa_csr[EE];        // per-CSR-slot: {src, edge_attr bits}
__device__ float g_logit_ovf[EE];     // overflow logits (k > CAP_L only)

// barrier state: count resets each use; gen grows monotonically across replays
__device__ int          g_bar_count = 0;
__device__ volatile int g_bar_gen   = 0;

__device__ __forceinline__ void grid_barrier() {
    __syncthreads();
    if (threadIdx.x == 0) {
        int gen = g_bar_gen;
        __threadfence();
        if (atomicAdd(&g_bar_count, 1) == NB - 1) {
            g_bar_count = 0;
            __threadfence();
            g_bar_gen = gen + 1;
        } else {
            while (g_bar_gen == gen) __nanosleep(64);
        }
        __threadfence();
    }
    __syncthreads();
}

// ---------------- K1: persistent CSR build + node GEMM ------------------------
// P0 zero counts | GB | P1 hist | GB | P2 local scan | GB | P3 offsets/cursor
// | GB | P4 scatter | P5 gemm (y = x@W + b_msg + b_edge)
__global__ void persist_kernel(const float* __restrict__ x, const int* __restrict__ ei,
                               const float* __restrict__ ea, const float* __restrict__ W,
                               const float* __restrict__ bm, const float* __restrict__ be) {
    extern __shared__ char dyn[];
    float* sW = (float*)dyn;                 // 4096 floats (P5 only)
    float* sx = (float*)(dyn + 16384);       // 128*65 floats (P5 only)
    int*   sA = (int*)(dyn + 16384);         // scan scratch (P2/P3), overlaps sx
    int*   sB = (int*)(dyn + 16384 + 1024);

    int t = threadIdx.x, b = blockIdx.x;
    int lane = t & 31, w = t >> 5;
    int gtid = b * NT + t;
    const int GSZ = NB * NT;

    // ---- P0: zero counts ----
    for (int i = gtid; i < NN; i += GSZ) g_counts[i] = 0;
    grid_barrier();

    // ---- P1: histogram of dst ----
    for (int e = gtid; e < EE; e += GSZ) atomicAdd(&g_counts[ei[EE + e]], 1);
    grid_barrier();

    // ---- P2: per-block local scan of CHUNK counts (2 per thread) ----
    int base = b * CHUNK;
    int idx0 = base + 2 * t, idx1 = idx0 + 1;
    int c0v = (2 * t     < CHUNK && idx0 < NN) ? g_counts[idx0] : 0;
    int c1v = (2 * t + 1 < CHUNK && idx1 < NN) ? g_counts[idx1] : 0;
    int v = c0v + c1v;
    int s = v;
#pragma unroll
    for (int d = 1; d < 32; d <<= 1) {
        int u = __shfl_up_sync(0xFFFFFFFFu, s, d);
        if (lane >= d) s += u;
    }
    if (lane == 31) sB[w] = s;
    __syncthreads();
    if (w == 0) {
        int ws = (lane < 8) ? sB[lane] : 0;
#pragma unroll
        for (int d = 1; d < 8; d <<= 1) {
            int u = __shfl_up_sync(0xFFFFFFFFu, ws, d);
            if (lane >= d) ws += u;
        }
        if (lane < 8) sB[lane] = ws;
    }
    __syncthreads();
    int excl = (w > 0 ? sB[w - 1] : 0) + s - v;      // block-local exclusive prefix
    if (t == 0) g_part[b] = sB[7];                   // block total
    grid_barrier();

    // ---- P3: prefix over block totals; write offsets + cursor ----
    sA[t] = (t < NB) ? g_part[t] : 0;
    __syncthreads();
    for (int d = 1; d < 256; d <<= 1) {              // Hillis-Steele inclusive
        int u = (t >= d) ? sA[t - d] : 0;
        __syncthreads();
        sA[t] += u;
        __syncthreads();
    }
    int bp = (b > 0) ? sA[b - 1] : 0;
    if (2 * t < CHUNK && idx0 < NN) { int o = excl + bp;       g_offsets[idx0] = o; g_cursor[idx0] = o; }
    if (2 * t + 1 < CHUNK && idx1 < NN) { int o = excl + c0v + bp; g_offsets[idx1] = o; g_cursor[idx1] = o; }
    grid_barrier();

    // ---- P4: scatter edges into CSR order ----
    for (int e = gtid; e < EE; e += GSZ) {
        int d = ei[EE + e];
        int p = atomicAdd(&g_cursor[d], 1);
        g_sa_csr[p] = make_int2(ei[e], __float_as_int(ea[e]));
    }

    // ---- P5: gemm, 128-row tiles, 4 rows x 8 cols per thread ----
    __syncthreads();                                 // sA/sx reuse safety
    for (int i = t; i < 1024; i += NT)
        ((float4*)sW)[i] = ((const float4*)W)[i];

    int q  = t >> 3;            // 0..31 -> rows q*4..q*4+3
    int cg = (t & 7) << 3;      // col group 0,8,...,56
    float bsum[8];
#pragma unroll
    for (int j = 0; j < 8; j++) bsum[j] = bm[cg + j] + be[cg + j];

    const int TILES = (NN + 127) >> 7;               // 391
    for (int tb = b; tb < TILES; tb += NB) {
        int r0 = tb << 7;
        __syncthreads();
        for (int i = t; i < 2048; i += NT) {
            int r = i >> 4, c4 = (i & 15) << 2;
            int gr = r0 + r;
            float4 vv = (gr < NN) ? ((const float4*)x)[(gr << 4) + (c4 >> 2)]
                                  : make_float4(0.f, 0.f, 0.f, 0.f);
            float* dst = sx + r * 65 + c4;
            dst[0] = vv.x; dst[1] = vv.y; dst[2] = vv.z; dst[3] = vv.w;
        }
        __syncthreads();

        float acc[4][8];
#pragma unroll
        for (int i = 0; i < 4; i++)
#pragma unroll
            for (int j = 0; j < 8; j++) acc[i][j] = 0.f;

#pragma unroll 4
        for (int k = 0; k < 64; k++) {
            const float* wr = sW + (k << 6) + cg;
            float4 w0 = *(const float4*)(wr);
            float4 w1 = *(const float4*)(wr + 4);
            float wv[8] = {w0.x, w0.y, w0.z, w0.w, w1.x, w1.y, w1.z, w1.w};
#pragma unroll
            for (int i = 0; i < 4; i++) {
                float xv = sx[(q * 4 + i) * 65 + k];
#pragma unroll
                for (int j = 0; j < 8; j++) acc[i][j] += xv * wv[j];
            }
        }

#pragma unroll
        for (int i = 0; i < 4; i++) {
            int gr = r0 + q * 4 + i;
            if (gr < NN) {
                float* yo = g_y + ((long)gr << 6) + cg;
                float4 o0 = make_float4(acc[i][0] + bsum[0], acc[i][1] + bsum[1],
                                        acc[i][2] + bsum[2], acc[i][3] + bsum[3]);
                float4 o1 = make_float4(acc[i][4] + bsum[4], acc[i][5] + bsum[5],
                                        acc[i][6] + bsum[6], acc[i][7] + bsum[7]);
                *(float4*)(yo)     = o0;
                *(float4*)(yo + 4) = o1;
            }
        }
    }
}

// ---------------- K2: fused logits + softmax + weighted segment-max ----------
__global__ void fused_kernel(const float* __restrict__ x, const float* __restrict__ We,
                             const float* __restrict__ att, float* __restrict__ out) {
    __shared__ float smsg[NWARP][CAP_E][64];   // 24 KB
    __shared__ float slog[NWARP][CAP_L];       // 1 KB
    int warp = threadIdx.x >> 5, lane = threadIdx.x & 31;
    int n = blockIdx.x * NWARP + warp;
    if (n >= NN) return;

    int off = g_offsets[n];
    int k   = g_counts[n];
    int c0  = lane << 1;

    float2 xv = *(const float2*)(x + ((long)n << 6) + c0);
    float o0 = xv.x, o1 = xv.y;

    if (k > 0) {
        // ---- pass 1: logits + msg-row cache (8 lanes/edge, 4 edges in flight) ----
        int g = lane >> 3, r = lane & 7;
        float4 we0 = ((const float4*)We)[r],  we1 = ((const float4*)We)[8 + r];
        float4 at0 = ((const float4*)att)[r], at1 = ((const float4*)att)[8 + r];
        for (int j0 = 0; j0 < k; j0 += 4) {
            int j = j0 + g;
            float v = 0.f;
            if (j < k) {
                int2 sa = g_sa_csr[off + j];
                float a = __int_as_float(sa.y);
                const float4* yr = (const float4*)(g_y + ((long)sa.x << 6));
                float4 y0 = yr[r], y1 = yr[8 + r];
                float4 m0, m1;
                m0.x = y0.x + a * we0.x; m0.y = y0.y + a * we0.y;
                m0.z = y0.z + a * we0.z; m0.w = y0.w + a * we0.w;
                m1.x = y1.x + a * we1.x; m1.y = y1.y + a * we1.y;
                m1.z = y1.z + a * we1.z; m1.w = y1.w + a * we1.w;
                v += fmaxf(m0.x, 0.2f * m0.x) * at0.x;
                v += fmaxf(m0.y, 0.2f * m0.y) * at0.y;
                v += fmaxf(m0.z, 0.2f * m0.z) * at0.z;
                v += fmaxf(m0.w, 0.2f * m0.w) * at0.w;
                v += fmaxf(m1.x, 0.2f * m1.x) * at1.x;
                v += fmaxf(m1.y, 0.2f * m1.y) * at1.y;
                v += fmaxf(m1.z, 0.2f * m1.z) * at1.z;
                v += fmaxf(m1.w, 0.2f * m1.w) * at1.w;
                if (j < CAP_E) {
                    *(float4*)&smsg[warp][j][r << 2]        = m0;
                    *(float4*)&smsg[warp][j][32 + (r << 2)] = m1;
                }
            }
            v += __shfl_xor_sync(0xFFFFFFFFu, v, 4);
            v += __shfl_xor_sync(0xFFFFFFFFu, v, 2);
            v += __shfl_xor_sync(0xFFFFFFFFu, v, 1);
            if (r == 0 && j < k) {
                if (j < CAP_L) slog[warp][j] = v;
                else           g_logit_ovf[off + j] = v;
            }
        }
        __syncwarp();

        // ---- softmax stats ----
        const float BIG = -1e30f;
        float mloc = BIG, sloc = 0.f;
        for (int i = lane; i < k; i += 32) {
            float l = (i < CAP_L) ? slog[warp][i] : g_logit_ovf[off + i];
            float nm = fmaxf(mloc, l);
            sloc = sloc * __expf(mloc - nm) + __expf(l - nm);
            mloc = nm;
        }
#pragma unroll
        for (int d = 16; d; d >>= 1) {
            float mo = __shfl_xor_sync(0xFFFFFFFFu, mloc, d);
            float so = __shfl_xor_sync(0xFFFFFFFFu, sloc, d);
            float mn = fmaxf(mloc, mo);
            sloc = sloc * __expf(mloc - mn) + so * __expf(mo - mn);
            mloc = mn;
        }
        float rden = 1.f / (sloc + 1e-16f);
        float m = mloc;

        // ---- pass 2: weighted max from smem ----
        float a0 = BIG, a1 = BIG;
        int jcap = (k < CAP_E) ? k : CAP_E;
        int j = 0;
        for (; j + 2 <= jcap; j += 2) {
            float2 v0 = *(const float2*)&smsg[warp][j    ][c0];
            float2 v1 = *(const float2*)&smsg[warp][j + 1][c0];
            float al0 = __expf(slog[warp][j    ] - m) * rden;
            float al1 = __expf(slog[warp][j + 1] - m) * rden;
            a0 = fmaxf(a0, v0.x * al0);
            a1 = fmaxf(a1, v0.y * al0);
            a0 = fmaxf(a0, v1.x * al1);
            a1 = fmaxf(a1, v1.y * al1);
        }
        for (; j < jcap; j++) {
            float2 v0 = *(const float2*)&smsg[warp][j][c0];
            float al = __expf(slog[warp][j] - m) * rden;
            a0 = fmaxf(a0, v0.x * al);
            a1 = fmaxf(a1, v0.y * al);
        }
        // overflow edges (k > CAP_E): re-gather from L2
        float2 we = *(const float2*)(We + c0);
        for (j = CAP_E; j < k; j++) {
            int2  sv = g_sa_csr[off + j];
            float l  = (j < CAP_L) ? slog[warp][j] : g_logit_ovf[off + j];
            float av = __int_as_float(sv.y);
            float alpha = __expf(l - m) * rden;
            float2 yv = *(const float2*)(g_y + ((long)sv.x << 6) + c0);
            a0 = fmaxf(a0, (yv.x + av * we.x) * alpha);
            a1 = fmaxf(a1, (yv.y + av * we.y) * alpha);
        }
        o0 += a0;
        o1 += a1;
    }
    *(float2*)(out + ((long)n << 6) + c0) = make_float2(o0, o1);
}

// ---------------- launch ------------------------------------------------------
extern "C" void kernel_launch(void* const* d_in, const int* in_sizes, int n_in,
                              void* d_out, int out_size) {
    const float* x   = (const float*)d_in[0];
    const int*   ei  = (const int*)d_in[1];
    const float* ea  = (const float*)d_in[2];
    const float* Wm  = (const float*)d_in[3];
    const float* bm  = (const float*)d_in[4];
    const float* We  = (const float*)d_in[5];
    const float* be  = (const float*)d_in[6];
    const float* att = (const float*)d_in[7];
    float*       out = (float*)d_out;
    (void)in_sizes; (void)n_in; (void)out_size;

    cudaFuncSetAttribute(persist_kernel,
                         cudaFuncAttributeMaxDynamicSharedMemorySize, SMEM_BYTES);
    persist_kernel<<<NB, NT, SMEM_BYTES>>>(x, ei, ea, Wm, bm, be);
    fused_kernel<<<(NN + NWARP - 1) / NWARP, NWARP * 32>>>(x, We, att, out);
}

// round 11
// speedup vs baseline: 1.0610x; 1.0610x over previous
#include <cuda_runtime.h>

#define NN 50000
#define EE 800000
#define NB 148            // persistent grid: <= SM count, all co-resident
#define NT 256
#define CHUNK 338         // ceil(NN / NB)
#define NWARP 8           // warps per block in fused kernel
#define SMEM_BYTES 49664  // sW 16384 + sx 33280

// ---------------- scratch (device globals; no allocations allowed) ----------
__device__ float g_y[NN * 64];        // y = x @ W_msg + (b_msg + b_edge)
__device__ int   g_counts[NN];
__device__ int   g_offsets[NN];
__device__ int   g_cursor[NN];
__device__ int   g_part[NB];
__device__ int2  g_sa_csr[EE];        // per-CSR-slot: {src, edge_attr bits}

// barrier state: count resets each use; gen grows monotonically across replays
__device__ int          g_bar_count = 0;
__device__ volatile int g_bar_gen   = 0;

__device__ __forceinline__ void grid_barrier() {
    __syncthreads();
    if (threadIdx.x == 0) {
        int gen = g_bar_gen;
        __threadfence();
        if (atomicAdd(&g_bar_count, 1) == NB - 1) {
            g_bar_count = 0;
            __threadfence();
            g_bar_gen = gen + 1;
        } else {
            while (g_bar_gen == gen) __nanosleep(64);
        }
        __threadfence();
    }
    __syncthreads();
}

// ---------------- K1: persistent CSR build + node GEMM ------------------------
__global__ void persist_kernel(const float* __restrict__ x, const int* __restrict__ ei,
                               const float* __restrict__ ea, const float* __restrict__ W,
                               const float* __restrict__ bm, const float* __restrict__ be) {
    extern __shared__ char dyn[];
    float* sW = (float*)dyn;                 // 4096 floats (P5 only)
    float* sx = (float*)(dyn + 16384);       // 128*65 floats (P5 only)
    int*   sA = (int*)(dyn + 16384);         // scan scratch (P2/P3), overlaps sx
    int*   sB = (int*)(dyn + 16384 + 1024);

    int t = threadIdx.x, b = blockIdx.x;
    int lane = t & 31, w = t >> 5;
    int gtid = b * NT + t;
    const int GSZ = NB * NT;

    // ---- P0: zero counts ----
    for (int i = gtid; i < NN; i += GSZ) g_counts[i] = 0;
    grid_barrier();

    // ---- P1: histogram of dst ----
    for (int e = gtid; e < EE; e += GSZ) atomicAdd(&g_counts[ei[EE + e]], 1);
    grid_barrier();

    // ---- P2: per-block local scan of CHUNK counts (2 per thread) ----
    int base = b * CHUNK;
    int idx0 = base + 2 * t, idx1 = idx0 + 1;
    int c0v = (2 * t     < CHUNK && idx0 < NN) ? g_counts[idx0] : 0;
    int c1v = (2 * t + 1 < CHUNK && idx1 < NN) ? g_counts[idx1] : 0;
    int v = c0v + c1v;
    int s = v;
#pragma unroll
    for (int d = 1; d < 32; d <<= 1) {
        int u = __shfl_up_sync(0xFFFFFFFFu, s, d);
        if (lane >= d) s += u;
    }
    if (lane == 31) sB[w] = s;
    __syncthreads();
    if (w == 0) {
        int ws = (lane < 8) ? sB[lane] : 0;
#pragma unroll
        for (int d = 1; d < 8; d <<= 1) {
            int u = __shfl_up_sync(0xFFFFFFFFu, ws, d);
            if (lane >= d) ws += u;
        }
        if (lane < 8) sB[lane] = ws;
    }
    __syncthreads();
    int excl = (w > 0 ? sB[w - 1] : 0) + s - v;      // block-local exclusive prefix
    if (t == 0) g_part[b] = sB[7];                   // block total
    grid_barrier();

    // ---- P3: prefix over block totals; write offsets + cursor ----
    sA[t] = (t < NB) ? g_part[t] : 0;
    __syncthreads();
    for (int d = 1; d < 256; d <<= 1) {              // Hillis-Steele inclusive
        int u = (t >= d) ? sA[t - d] : 0;
        __syncthreads();
        sA[t] += u;
        __syncthreads();
    }
    int bp = (b > 0) ? sA[b - 1] : 0;
    if (2 * t < CHUNK && idx0 < NN) { int o = excl + bp;           g_offsets[idx0] = o; g_cursor[idx0] = o; }
    if (2 * t + 1 < CHUNK && idx1 < NN) { int o = excl + c0v + bp; g_offsets[idx1] = o; g_cursor[idx1] = o; }
    grid_barrier();

    // ---- P4: scatter edges into CSR order ----
    for (int e = gtid; e < EE; e += GSZ) {
        int d = ei[EE + e];
        int p = atomicAdd(&g_cursor[d], 1);
        g_sa_csr[p] = make_int2(ei[e], __float_as_int(ea[e]));
    }

    // ---- P5: gemm, 128-row tiles, 4 rows x 8 cols per thread ----
    __syncthreads();
    for (int i = t; i < 1024; i += NT)
        ((float4*)sW)[i] = ((const float4*)W)[i];

    int q  = t >> 3;
    int cg = (t & 7) << 3;
    float bsum[8];
#pragma unroll
    for (int j = 0; j < 8; j++) bsum[j] = bm[cg + j] + be[cg + j];

    const int TILES = (NN + 127) >> 7;
    for (int tb = b; tb < TILES; tb += NB) {
        int r0 = tb << 7;
        __syncthreads();
        for (int i = t; i < 2048; i += NT) {
            int r = i >> 4, c4 = (i & 15) << 2;
            int gr = r0 + r;
            float4 vv = (gr < NN) ? ((const float4*)x)[(gr << 4) + (c4 >> 2)]
                                  : make_float4(0.f, 0.f, 0.f, 0.f);
            float* dst = sx + r * 65 + c4;
            dst[0] = vv.x; dst[1] = vv.y; dst[2] = vv.z; dst[3] = vv.w;
        }
        __syncthreads();

        float acc[4][8];
#pragma unroll
        for (int i = 0; i < 4; i++)
#pragma unroll
            for (int j = 0; j < 8; j++) acc[i][j] = 0.f;

#pragma unroll 4
        for (int k = 0; k < 64; k++) {
            const float* wr = sW + (k << 6) + cg;
            float4 w0 = *(const float4*)(wr);
            float4 w1 = *(const float4*)(wr + 4);
            float wv[8] = {w0.x, w0.y, w0.z, w0.w, w1.x, w1.y, w1.z, w1.w};
#pragma unroll
            for (int i = 0; i < 4; i++) {
                float xv = sx[(q * 4 + i) * 65 + k];
#pragma unroll
                for (int j = 0; j < 8; j++) acc[i][j] += xv * wv[j];
            }
        }

#pragma unroll
        for (int i = 0; i < 4; i++) {
            int gr = r0 + q * 4 + i;
            if (gr < NN) {
                float* yo = g_y + ((long)gr << 6) + cg;
                float4 o0 = make_float4(acc[i][0] + bsum[0], acc[i][1] + bsum[1],
                                        acc[i][2] + bsum[2], acc[i][3] + bsum[3]);
                float4 o1 = make_float4(acc[i][4] + bsum[4], acc[i][5] + bsum[5],
                                        acc[i][6] + bsum[6], acc[i][7] + bsum[7]);
                *(float4*)(yo)     = o0;
                *(float4*)(yo + 4) = o1;
            }
        }
    }
}

// ---------------- K2: single-pass fused softmax + weighted segment-max -------
// warp per dst node; 4 groups of 8 lanes, each group streams every 4th edge.
// Online flash-style rescaling keeps everything in registers.
__global__ void fused_kernel(const float* __restrict__ x, const float* __restrict__ We,
                             const float* __restrict__ att, float* __restrict__ out) {
    int warp = threadIdx.x >> 5, lane = threadIdx.x & 31;
    int n = blockIdx.x * NWARP + warp;
    if (n >= NN) return;

    int off = g_offsets[n];
    int k   = g_counts[n];
    int g   = lane >> 3, r = lane & 7;
    unsigned gm = 0xFFu << (g << 3);          // this group's 8-lane shfl mask

    const float BIG = -1e30f;
    float mcur = BIG, scur = 0.f;
    float4 A0 = make_float4(0.f, 0.f, 0.f, 0.f);
    float4 A1 = make_float4(0.f, 0.f, 0.f, 0.f);

    if (k > 0) {
        float4 we0 = ((const float4*)We)[r],  we1 = ((const float4*)We)[8 + r];
        float4 at0 = ((const float4*)att)[r], at1 = ((const float4*)att)[8 + r];

        for (int j = g; j < k; j += 4) {
            int2 sa = g_sa_csr[off + j];
            float a = __int_as_float(sa.y);
            const float4* yr = (const float4*)(g_y + ((long)sa.x << 6));
            float4 y0 = yr[r], y1 = yr[8 + r];
            float4 m0, m1;
            m0.x = fmaf(a, we0.x, y0.x); m0.y = fmaf(a, we0.y, y0.y);
            m0.z = fmaf(a, we0.z, y0.z); m0.w = fmaf(a, we0.w, y0.w);
            m1.x = fmaf(a, we1.x, y1.x); m1.y = fmaf(a, we1.y, y1.y);
            m1.z = fmaf(a, we1.z, y1.z); m1.w = fmaf(a, we1.w, y1.w);

            float v = 0.f;
            v += fmaxf(m0.x, 0.2f * m0.x) * at0.x;
            v += fmaxf(m0.y, 0.2f * m0.y) * at0.y;
            v += fmaxf(m0.z, 0.2f * m0.z) * at0.z;
            v += fmaxf(m0.w, 0.2f * m0.w) * at0.w;
            v += fmaxf(m1.x, 0.2f * m1.x) * at1.x;
            v += fmaxf(m1.y, 0.2f * m1.y) * at1.y;
            v += fmaxf(m1.z, 0.2f * m1.z) * at1.z;
            v += fmaxf(m1.w, 0.2f * m1.w) * at1.w;
            v += __shfl_xor_sync(gm, v, 4);
            v += __shfl_xor_sync(gm, v, 2);
            v += __shfl_xor_sync(gm, v, 1);

            if (j < 4) {                       // first edge of this group
                mcur = v; scur = 1.f;
                A0 = m0; A1 = m1;
            } else {                           // online rescale + max
                float nm = fmaxf(mcur, v);
                float cs = __expf(mcur - nm);
                float e  = __expf(v - nm);
                scur = scur * cs + e;
                A0.x = fmaxf(A0.x * cs, m0.x * e);
                A0.y = fmaxf(A0.y * cs, m0.y * e);
                A0.z = fmaxf(A0.z * cs, m0.z * e);
                A0.w = fmaxf(A0.w * cs, m0.w * e);
                A1.x = fmaxf(A1.x * cs, m1.x * e);
                A1.y = fmaxf(A1.y * cs, m1.y * e);
                A1.z = fmaxf(A1.z * cs, m1.z * e);
                A1.w = fmaxf(A1.w * cs, m1.w * e);
                mcur = nm;
            }
        }

        // ---- combine the 4 groups (whole warp reconverged here) ----
        float mg = fmaxf(mcur, __shfl_xor_sync(0xFFFFFFFFu, mcur, 8));
        mg = fmaxf(mg, __shfl_xor_sync(0xFFFFFFFFu, mg, 16));

        bool empty = (mcur == BIG);
        float f = empty ? 0.f : __expf(mcur - mg);
        float sg = scur * f;
        sg += __shfl_xor_sync(0xFFFFFFFFu, sg, 8);
        sg += __shfl_xor_sync(0xFFFFFFFFu, sg, 16);

        A0.x = empty ? BIG : A0.x * f;  A0.y = empty ? BIG : A0.y * f;
        A0.z = empty ? BIG : A0.z * f;  A0.w = empty ? BIG : A0.w * f;
        A1.x = empty ? BIG : A1.x * f;  A1.y = empty ? BIG : A1.y * f;
        A1.z = empty ? BIG : A1.z * f;  A1.w = empty ? BIG : A1.w * f;
#pragma unroll
        for (int d = 8; d <= 16; d <<= 1) {
            A0.x = fmaxf(A0.x, __shfl_xor_sync(0xFFFFFFFFu, A0.x, d));
            A0.y = fmaxf(A0.y, __shfl_xor_sync(0xFFFFFFFFu, A0.y, d));
            A0.z = fmaxf(A0.z, __shfl_xor_sync(0xFFFFFFFFu, A0.z, d));
            A0.w = fmaxf(A0.w, __shfl_xor_sync(0xFFFFFFFFu, A0.w, d));
            A1.x = fmaxf(A1.x, __shfl_xor_sync(0xFFFFFFFFu, A1.x, d));
            A1.y = fmaxf(A1.y, __shfl_xor_sync(0xFFFFFFFFu, A1.y, d));
            A1.z = fmaxf(A1.z, __shfl_xor_sync(0xFFFFFFFFu, A1.z, d));
            A1.w = fmaxf(A1.w, __shfl_xor_sync(0xFFFFFFFFu, A1.w, d));
        }
        float rden = 1.f / (sg + 1e-16f);
        A0.x *= rden; A0.y *= rden; A0.z *= rden; A0.w *= rden;
        A1.x *= rden; A1.y *= rden; A1.z *= rden; A1.w *= rden;
    }

    if (g == 0) {                              // 8 lanes write 8 dims each
        float4 xv0 = ((const float4*)x)[(n << 4) + r];
        float4 xv1 = ((const float4*)x)[(n << 4) + 8 + r];
        float4 o0, o1;
        if (k > 0) {
            o0 = make_float4(A0.x + xv0.x, A0.y + xv0.y, A0.z + xv0.z, A0.w + xv0.w);
            o1 = make_float4(A1.x + xv1.x, A1.y + xv1.y, A1.z + xv1.z, A1.w + xv1.w);
        } else {
            o0 = xv0; o1 = xv1;
        }
        ((float4*)out)[(n << 4) + r]     = o0;
        ((float4*)out)[(n << 4) + 8 + r] = o1;
    }
}

// ---------------- launch ------------------------------------------------------
extern "C" void kernel_launch(void* const* d_in, const int* in_sizes, int n_in,
                              void* d_out, int out_size) {
    const float* x   = (const float*)d_in[0];
    const int*   ei  = (const int*)d_in[1];
    const float* ea  = (const float*)d_in[2];
    const float* Wm  = (const float*)d_in[3];
    const float* bm  = (const float*)d_in[4];
    const float* We  = (const float*)d_in[5];
    const float* be  = (const float*)d_in[6];
    const float* att = (const float*)d_in[7];
    float*       out = (float*)d_out;
    (void)in_sizes; (void)n_in; (void)out_size;

    cudaFuncSetAttribute(persist_kernel,
                         cudaFuncAttributeMaxDynamicSharedMemorySize, SMEM_BYTES);
    persist_kernel<<<NB, NT, SMEM_BYTES>>>(x, ei, ea, Wm, bm, be);
    fused_kernel<<<(NN + NWARP - 1) / NWARP, NWARP * 32>>>(x, We, att, out);
}